// round 14
// baseline (speedup 1.0000x reference)
#include <cuda_runtime.h>
#include <cuda_bf16.h>
#include <math.h>
#include <stdint.h>

// ---------------- problem constants ----------------
#define BB 4
#define SS 4096
#define EE 512
#define HH 8
#define LL 4
#define AA 3
#define WIN 64
#define CC 64           // S / WIN clusters
#define DD 64           // E / H
#define MM (BB*SS)      // 16384 rows
#define FF (4*EE)       // 2048 ffn dim
#define QKS (3*EE)      // fused qkv row stride 1536
#define NVOC 17

// ---------------- scratch (device globals; no allocation allowed) ----------------
__device__ float g_x[MM*EE];
__device__ float g_qkv[MM*QKS];
__device__ float g_dists[BB*HH*CC*SS];
__device__ float g_attout[MM*EE];
__device__ float g_cnt[MM*HH];
// split activations (A operands)
__device__ __nv_bfloat16 g_hh[MM*EE],  g_hl[MM*EE];
__device__ __nv_bfloat16 g_th[MM*FF],  g_tl[MM*FF];
__device__ __nv_bfloat16 g_aoh[MM*EE], g_aol[MM*EE];
// split weights, pair-interleaved: uint32 [K/2][N] per layer
__device__ uint32_t g_Wqkvh[LL*(EE/2)*QKS], g_Wqkvl[LL*(EE/2)*QKS];
__device__ uint32_t g_Woh[LL*(EE/2)*EE],    g_Wol[LL*(EE/2)*EE];
__device__ uint32_t g_W1h[LL*(EE/2)*FF],    g_W1l[LL*(EE/2)*FF];
__device__ uint32_t g_W2h[LL*(FF/2)*EE],    g_W2l[LL*(FF/2)*EE];

// ---------------- bf16 split helpers ----------------
__device__ __forceinline__ uint32_t packbf(float x, float y) {
    __nv_bfloat162 t = __floats2bfloat162_rn(x, y);
    return *reinterpret_cast<uint32_t*>(&t);
}
__device__ __forceinline__ void split2(float x, float y, uint32_t& hi, uint32_t& lo) {
    float xh = __bfloat162float(__float2bfloat16(x));
    float yh = __bfloat162float(__float2bfloat16(y));
    hi = packbf(x, y);
    lo = packbf(x - xh, y - yh);
}
__device__ __forceinline__ void split1(float x, __nv_bfloat16& h, __nv_bfloat16& l) {
    h = __float2bfloat16(x);
    l = __float2bfloat16(x - __bfloat162float(h));
}

// ---------------- merged weight split prep (single launch) ----------------
__device__ __forceinline__ void split_pi_item(const float* __restrict__ W,
                                              uint32_t* __restrict__ PIh, uint32_t* __restrict__ PIl,
                                              int K, int N, int gid) {
    int i = gid*4;
    int c = i % N;
    int rest = i / N;
    int p = rest % (K/2);
    int l = rest / (K/2);
    const float* w0 = W + ((size_t)l*K + 2*p)*N + c;
    float4 v0 = *(const float4*)w0;
    float4 v1 = *(const float4*)(w0 + N);
    uint32_t h0,l0,h1,l1,h2,l2,h3,l3;
    split2(v0.x, v1.x, h0, l0);
    split2(v0.y, v1.y, h1, l1);
    split2(v0.z, v1.z, h2, l2);
    split2(v0.w, v1.w, h3, l3);
    size_t o = ((size_t)l*(K/2) + p)*N + c;
    *(uint4*)(PIh + o) = make_uint4(h0,h1,h2,h3);
    *(uint4*)(PIl + o) = make_uint4(l0,l1,l2,l3);
}

#define SPLIT_BLOCKS 6144
__global__ void split_all_kernel(const float* __restrict__ Wq, const float* __restrict__ Wk,
                                 const float* __restrict__ Wv, const float* __restrict__ Wo,
                                 const float* __restrict__ W1, const float* __restrict__ W2,
                                 uint32_t* __restrict__ Wqkvh, uint32_t* __restrict__ Wqkvl,
                                 uint32_t* __restrict__ Woh, uint32_t* __restrict__ Wol,
                                 uint32_t* __restrict__ W1h, uint32_t* __restrict__ W1l,
                                 uint32_t* __restrict__ W2h, uint32_t* __restrict__ W2l) {
    int blk = blockIdx.x;
    int tid = threadIdx.x;
    if (blk < 1536) {
        int gid = blk*256 + tid;
        int i = gid*4;
        int c = i % QKS;
        int rest = i / QKS;
        int p = rest % (EE/2);
        int l = rest / (EE/2);
        const float* src; int cc = c;
        if (c < EE) src = Wq;
        else if (c < 2*EE) { src = Wk; cc = c - EE; }
        else { src = Wv; cc = c - 2*EE; }
        const float* w0 = src + ((size_t)l*EE + 2*p)*EE + cc;
        float4 v0 = *(const float4*)w0;
        float4 v1 = *(const float4*)(w0 + EE);
        uint32_t h0,l0,h1,l1,h2,l2,h3,l3;
        split2(v0.x, v1.x, h0, l0);
        split2(v0.y, v1.y, h1, l1);
        split2(v0.z, v1.z, h2, l2);
        split2(v0.w, v1.w, h3, l3);
        size_t o = ((size_t)l*(EE/2) + p)*QKS + c;
        *(uint4*)(Wqkvh + o) = make_uint4(h0,h1,h2,h3);
        *(uint4*)(Wqkvl + o) = make_uint4(l0,l1,l2,l3);
    } else if (blk < 2048) {
        split_pi_item(Wo, Woh, Wol, EE, EE, (blk-1536)*256 + tid);
    } else if (blk < 4096) {
        split_pi_item(W1, W1h, W1l, EE, FF, (blk-2048)*256 + tid);
    } else {
        split_pi_item(W2, W2h, W2l, FF, EE, (blk-4096)*256 + tid);
    }
}

// ---------------- embedding + shift-right ----------------
__global__ void embed_kernel(const int* __restrict__ value, const int* __restrict__ depth,
                             const int* __restrict__ pos, const float* __restrict__ sos,
                             const float* __restrict__ tok, const float* __restrict__ dep,
                             const float* __restrict__ pemb, float* __restrict__ x) {
    int row = blockIdx.x;
    int t = row & (SS - 1);
    if (t == 0) {
        for (int e = threadIdx.x; e < EE; e += blockDim.x) x[(size_t)row*EE + e] = sos[e];
        return;
    }
    int pr = row - 1;
    int v  = value[pr], dp = depth[pr];
    int p0 = pos[pr*AA+0], p1 = pos[pr*AA+1], p2 = pos[pr*AA+2];
    for (int e = threadIdx.x; e < EE; e += blockDim.x) {
        float s = tok[v*EE+e] + dep[dp*EE+e]
                + pemb[(0*65 + p0)*EE + e]
                + pemb[(1*65 + p1)*EE + e]
                + pemb[(2*65 + p2)*EE + e];
        x[(size_t)row*EE + e] = s;
    }
}

// ---------------- layernorm: warp per row, no smem ----------------
__global__ void ln_kernel(const float* __restrict__ x, const float* __restrict__ sc,
                          const float* __restrict__ bi,
                          __nv_bfloat16* __restrict__ oh, __nv_bfloat16* __restrict__ ol) {
    int warp = threadIdx.x >> 5, lane = threadIdx.x & 31;
    int row = blockIdx.x*8 + warp;
    const float4* xr = (const float4*)(x + (size_t)row*EE);
    float4 v[4];
    float s = 0.0f, q2 = 0.0f;
#pragma unroll
    for (int i = 0; i < 4; i++) {
        v[i] = xr[lane + 32*i];
        s  += v[i].x + v[i].y + v[i].z + v[i].w;
        q2 += v[i].x*v[i].x + v[i].y*v[i].y + v[i].z*v[i].z + v[i].w*v[i].w;
    }
#pragma unroll
    for (int o = 16; o; o >>= 1) {
        s  += __shfl_xor_sync(0xffffffffu, s, o);
        q2 += __shfl_xor_sync(0xffffffffu, q2, o);
    }
    float m = s * (1.0f/EE);
    float r = rsqrtf(q2 * (1.0f/EE) - m*m + 1e-5f);
#pragma unroll
    for (int i = 0; i < 4; i++) {
        int c4 = (lane + 32*i) * 4;
        float y0 = (v[i].x - m)*r*sc[c4+0] + bi[c4+0];
        float y1 = (v[i].y - m)*r*sc[c4+1] + bi[c4+1];
        float y2 = (v[i].z - m)*r*sc[c4+2] + bi[c4+2];
        float y3 = (v[i].w - m)*r*sc[c4+3] + bi[c4+3];
        uint32_t hA, lA, hB, lB;
        split2(y0, y1, hA, lA);
        split2(y2, y3, hB, lB);
        *(uint2*)(oh + (size_t)row*EE + c4) = make_uint2(hA, hB);
        *(uint2*)(ol + (size_t)row*EE + c4) = make_uint2(lA, lB);
    }
}

// ---------------- gelu ----------------
__device__ __forceinline__ float gelu_f(float x) {
    float x3 = x*x*x;
    return 0.5f*x*(1.0f + tanhf(0.7978845608028654f*(x + 0.044715f*x3)));
}

__device__ __forceinline__ void mma_bf16(float d[4], const uint32_t a[4], const uint32_t b[2]) {
    asm volatile(
        "mma.sync.aligned.m16n8k16.row.col.f32.bf16.bf16.f32 "
        "{%0,%1,%2,%3}, {%4,%5,%6,%7}, {%8,%9}, {%0,%1,%2,%3};\n"
        : "+f"(d[0]), "+f"(d[1]), "+f"(d[2]), "+f"(d[3])
        : "r"(a[0]), "r"(a[1]), "r"(a[2]), "r"(a[3]), "r"(b[0]), "r"(b[1]));
}

__device__ __forceinline__ void ldsm4(uint32_t f[4], uint32_t smaddr) {
    asm volatile("ldmatrix.sync.aligned.m8n8.x4.shared.b16 {%0,%1,%2,%3}, [%4];"
                 : "=r"(f[0]), "=r"(f[1]), "=r"(f[2]), "=r"(f[3]) : "r"(smaddr));
}

__device__ __forceinline__ void cpa16(uint32_t dst, const void* src) {
    asm volatile("cp.async.cg.shared.global [%0], [%1], 16;" :: "r"(dst), "l"(src));
}
#define CP_COMMIT() asm volatile("cp.async.commit_group;")
#define CP_WAIT2()  asm volatile("cp.async.wait_group 2;")

// ---------------- split-bf16 tensor GEMM: 4-stage cp.async, phase-staged frags ----------------
#define AST 12
#define BST 136
#define STA (128*AST)
#define STB (8*BST)
#define NSTG 4
#define GEMM_SMEM ((NSTG*(STA*2 + STB*2))*4)

template<int ACT, int OUTMODE, bool HASB>
__global__ void __launch_bounds__(256,2) bf3_gemm(
    const __nv_bfloat16* __restrict__ Ah, const __nv_bfloat16* __restrict__ Al,
    const uint32_t* __restrict__ Bh, const uint32_t* __restrict__ Bl,
    const float* __restrict__ bias,
    float* __restrict__ C,
    __nv_bfloat16* __restrict__ Ch, __nv_bfloat16* __restrict__ Cl,
    int M, int N, int K)
{
    extern __shared__ uint32_t gsm[];
    uint32_t* AsH = gsm;
    uint32_t* AsL = AsH + NSTG*STA;
    uint32_t* BsH = AsL + NSTG*STA;
    uint32_t* BsL = BsH + NSTG*STB;

    int tid = threadIdx.x;
    int lane = tid & 31;
    int warp = tid >> 5;
    int wm = (warp >> 2) * 64;
    int wn = (warp & 3) * 32;
    int bm = blockIdx.y * 128, bn = blockIdx.x * 128;

    float acc[4][4][4];
#pragma unroll
    for (int mi = 0; mi < 4; mi++)
#pragma unroll
        for (int ni = 0; ni < 4; ni++)
#pragma unroll
            for (int r = 0; r < 4; r++) acc[mi][ni][r] = 0.0f;

    int a_r = tid >> 1, a_h = (tid & 1) * 8;
    int b_p = tid >> 5, b_cg = (tid & 31) * 4;
    const __nv_bfloat16* Abh = Ah + (size_t)bm*K + (size_t)a_r*K + a_h;
    const __nv_bfloat16* Abl = Al + (size_t)bm*K + (size_t)a_r*K + a_h;
    const uint32_t* Bbh = Bh + (size_t)b_p*N + bn + b_cg;
    const uint32_t* Bbl = Bl + (size_t)b_p*N + bn + b_cg;

    uint32_t awH = (uint32_t)__cvta_generic_to_shared(AsH) + (a_r*AST + (a_h>>1))*4;
    uint32_t awL = (uint32_t)__cvta_generic_to_shared(AsL) + (a_r*AST + (a_h>>1))*4;
    uint32_t bwH = (uint32_t)__cvta_generic_to_shared(BsH) + (b_p*BST + b_cg)*4;
    uint32_t bwL = (uint32_t)__cvta_generic_to_shared(BsL) + (b_p*BST + b_cg)*4;

    int nk = K / 16;

#define ISSUE(S, K0)                                              \
    {                                                             \
        cpa16(awH + (S)*STA*4, Abh + (K0));                       \
        cpa16(awL + (S)*STA*4, Abl + (K0));                       \
        cpa16(bwH + (S)*STB*4, Bbh + (size_t)((K0)>>1)*N);        \
        cpa16(bwL + (S)*STB*4, Bbl + (size_t)((K0)>>1)*N);        \
    }

    ISSUE(0, 0)  CP_COMMIT();
    ISSUE(1, 16) CP_COMMIT();
    ISSUE(2, 32) CP_COMMIT();

    int l_row = wm + (lane & 7) + ((lane >> 3) & 1) * 8;
    int l_kp  = ((lane >> 4) & 1) * 4;
    uint32_t aoffH = (uint32_t)__cvta_generic_to_shared(AsH) + (l_row*AST + l_kp)*4;
    uint32_t aoffL = (uint32_t)__cvta_generic_to_shared(AsL) + (l_row*AST + l_kp)*4;

    int bc0 = wn + (lane >> 2);
    int bp0 = lane & 3;

    for (int it = 0; it < nk; it++) {
        int buf = it & (NSTG-1);
        CP_WAIT2();
        __syncthreads();
        // prefetch next stage as early as possible
        if (it + 3 < nk) ISSUE((it+3) & (NSTG-1), (it+3)*16)
        CP_COMMIT();

        uint32_t aH = aoffH + (uint32_t)buf*STA*4;
        uint32_t aL = aoffL + (uint32_t)buf*STA*4;
        const uint32_t* bsH = BsH + buf*STB;
        const uint32_t* bsL = BsL + buf*STB;

        // phase 1: hi x hi
        uint32_t afh[4][4], bfh[4][2];
#pragma unroll
        for (int mi = 0; mi < 4; mi++) ldsm4(afh[mi], aH + (uint32_t)(mi*16*AST*4));
#pragma unroll
        for (int ni = 0; ni < 4; ni++) {
            int base = bp0*BST + bc0 + ni*8;
            bfh[ni][0] = bsH[base];
            bfh[ni][1] = bsH[base + 4*BST];
        }
#pragma unroll
        for (int mi = 0; mi < 4; mi++)
#pragma unroll
            for (int ni = 0; ni < 4; ni++) mma_bf16(acc[mi][ni], afh[mi], bfh[ni]);
        // phase 2: lo x hi (afl live only here)
        {
            uint32_t afl[4][4];
#pragma unroll
            for (int mi = 0; mi < 4; mi++) ldsm4(afl[mi], aL + (uint32_t)(mi*16*AST*4));
#pragma unroll
            for (int mi = 0; mi < 4; mi++)
#pragma unroll
                for (int ni = 0; ni < 4; ni++) mma_bf16(acc[mi][ni], afl[mi], bfh[ni]);
        }
        // phase 3: hi x lo (bfl live only here)
        {
            uint32_t bfl[4][2];
#pragma unroll
            for (int ni = 0; ni < 4; ni++) {
                int base = bp0*BST + bc0 + ni*8;
                bfl[ni][0] = bsL[base];
                bfl[ni][1] = bsL[base + 4*BST];
            }
#pragma unroll
            for (int mi = 0; mi < 4; mi++)
#pragma unroll
                for (int ni = 0; ni < 4; ni++) mma_bf16(acc[mi][ni], afh[mi], bfl[ni]);
        }
    }

#pragma unroll
    for (int mi = 0; mi < 4; mi++) {
        int r0 = bm + wm + mi*16 + (lane >> 2);
#pragma unroll
        for (int ni = 0; ni < 4; ni++) {
            int c0 = bn + wn + ni*8 + (lane & 3)*2;
            float* a = acc[mi][ni];
#pragma unroll
            for (int hr = 0; hr < 2; hr++) {
                int r = r0 + hr*8;
                float v0 = a[hr*2 + 0], v1 = a[hr*2 + 1];
                if (HASB) { v0 += bias[c0]; v1 += bias[c0+1]; }
                if (ACT == 1) { v0 = gelu_f(v0); v1 = gelu_f(v1); }
                size_t o = (size_t)r*N + c0;
                if (OUTMODE == 0) {
                    float2 t2; t2.x = v0; t2.y = v1;
                    *(float2*)&C[o] = t2;
                } else if (OUTMODE == 1) {
                    float2 old = *(float2*)&C[o];
                    old.x += v0; old.y += v1;
                    *(float2*)&C[o] = old;
                } else {
                    uint32_t hh2, ll2;
                    split2(v0, v1, hh2, ll2);
                    *(uint32_t*)&Ch[o] = hh2;
                    *(uint32_t*)&Cl[o] = ll2;
                }
            }
        }
    }
}

// ---------------- fused qnorm + cluster distances (tiled; q has QKS stride) ----------------
__global__ void dist_kernel(const float* __restrict__ q, const float* __restrict__ means_l,
                            float* __restrict__ dists) {
    extern __shared__ float dsm[];
    float* qs = dsm;
    float* ms = qs + 128*65;
    float* mn = ms + 64*64;
    float* qn = mn + 64;
    int tile = blockIdx.x;
    int bh = blockIdx.y;
    int h = bh & 7, b = bh >> 3;
    int n0 = tile * 128;
    int tid = threadIdx.x;
    for (int i = tid; i < 64*64; i += 256) ms[i] = means_l[h*64*64 + i];
    for (int i = tid; i < 128*16; i += 256) {
        int r = i >> 4, c4 = (i & 15) * 4;
        float4 v = *(const float4*)(q + ((size_t)(b*SS + n0 + r))*QKS + h*DD + c4);
        float* dst = qs + r*65 + c4;
        dst[0]=v.x; dst[1]=v.y; dst[2]=v.z; dst[3]=v.w;
    }
    __syncthreads();
    if (tid < 64) {
        float s = 0; const float* mr = ms + tid*64;
#pragma unroll 16
        for (int d = 0; d < 64; d++) s += mr[d]*mr[d];
        mn[tid] = 1.0f/(sqrtf(s) + 1e-8f);
    } else if (tid >= 128) {
        int r = tid - 128;
        float s = 0; const float* qr = qs + r*65;
#pragma unroll 16
        for (int d = 0; d < 64; d++) s += qr[d]*qr[d];
        qn[r] = 1.0f/(sqrtf(s) + 1e-8f);
    }
    __syncthreads();
    int nl = tid & 127;
    int c0 = (tid >> 7) * 32;
    float acc[32];
#pragma unroll
    for (int c = 0; c < 32; c++) acc[c] = 0.0f;
    for (int dc = 0; dc < 64; dc += 16) {
        float qreg[16];
#pragma unroll
        for (int d = 0; d < 16; d++) qreg[d] = qs[nl*65 + dc + d];
#pragma unroll
        for (int c = 0; c < 32; c++) {
            const float* mr = ms + (c0 + c)*64 + dc;
            float s = acc[c];
#pragma unroll
            for (int d = 0; d < 16; d++) s += qreg[d]*mr[d];
            acc[c] = s;
        }
    }
    float qi = qn[nl];
#pragma unroll
    for (int c = 0; c < 32; c++) {
        int cc = c0 + c;
        dists[((size_t)bh*CC + cc)*SS + n0 + nl] = acc[c]*mn[cc]*qi;
    }
}

// ---------------- FUSED radix-top64 + bucket attention ----------------
// dynamic smem: attn arrays (4 * 64*65 floats). topk phase overlays the front:
//   keys = (uint32*)sm [0, 16KB), ties = (int*)(sm + 16KB) [16KB, 32KB)
__global__ void topk_attn_kernel(const float* __restrict__ dists,
                                 const float* __restrict__ q, const float* __restrict__ k,
                                 const float* __restrict__ v, const int* __restrict__ value,
                                 float* __restrict__ attout, float* __restrict__ cnt) {
    extern __shared__ float sm[];
    float* qb = sm;
    float* kb = qb + 64*65;
    float* vb = kb + 64*65;
    float* sc = vb + 64*65;
    __shared__ int idxs[64];
    __shared__ int kms[64];
    __shared__ int hist[256];
    __shared__ int rmin[256];
    __shared__ int s_chosen, s_rem, s_cntgt, s_ntie, s_pick;
    int blk = blockIdx.x;              // (b*H + h)*C + c
    int bh = blk / CC; int h = bh % HH; int b = bh / HH;
    int tid = threadIdx.x;

    // ---- phase A: radix-select top-64 of this cluster's dist row ----
    {
        uint32_t* keys = (uint32_t*)sm;
        int* ties = (int*)(sm + SS);
        const float* drow = dists + (size_t)blk*SS;
        for (int n = tid; n < SS; n += 256) {
            uint32_t u = __float_as_uint(drow[n]);
            keys[n] = (u & 0x80000000u) ? ~u : (u | 0x80000000u);
        }
        uint32_t prefix = 0, maskhi = 0;
        int rem = WIN;
        for (int p = 0; p < 4; p++) {
            int shift = 24 - 8*p;
            hist[tid] = 0;
            __syncthreads();
            for (int n = tid; n < SS; n += 256) {
                uint32_t kk = keys[n];
                if ((kk & maskhi) == prefix) atomicAdd(&hist[(kk >> shift) & 255], 1);
            }
            __syncthreads();
            if (tid == 0) {
                int cum = 0, bsel = 255;
                for (; bsel >= 0; bsel--) { cum += hist[bsel]; if (cum >= rem) break; }
                s_chosen = bsel; s_rem = rem - (cum - hist[bsel]);
            }
            __syncthreads();
            prefix |= ((uint32_t)s_chosen) << shift;
            maskhi |= 0xFFu << shift;
            rem = s_rem;
            __syncthreads();
        }
        uint32_t T = prefix;
        if (tid == 0) { s_cntgt = 0; s_ntie = 0; }
        __syncthreads();
        for (int n = tid; n < SS; n += 256) {
            uint32_t kk = keys[n];
            if (kk > T) { int pp = atomicAdd(&s_cntgt, 1); idxs[pp] = n; }
            else if (kk == T) { int pp = atomicAdd(&s_ntie, 1); ties[pp] = n; }
        }
        __syncthreads();
        int cntgt = s_cntgt;
        int need = WIN - cntgt;
        int ntie = s_ntie;
        if (need > 0) {
            if (need == ntie) {
                for (int j = tid; j < need; j += 256) idxs[cntgt + j] = ties[j];
                __syncthreads();
            } else {
                int last = -1;
                for (int j = 0; j < need; j++) {
                    int mymin = 0x7FFFFFFF;
                    for (int t2 = tid; t2 < ntie; t2 += 256) {
                        int vv = ties[t2];
                        if (vv > last && vv < mymin) mymin = vv;
                    }
                    rmin[tid] = mymin;
                    __syncthreads();
                    for (int off = 128; off; off >>= 1) {
                        if (tid < off) rmin[tid] = min(rmin[tid], rmin[tid+off]);
                        __syncthreads();
                    }
                    if (tid == 0) { idxs[cntgt + j] = rmin[0]; s_pick = rmin[0]; }
                    __syncthreads();
                    last = s_pick;
                }
            }
        } else {
            __syncthreads();
        }
    }
    // ---- phase B: bucket attention (keys/ties regions now reused as qb/kb) ----
    if (tid < 64) kms[tid] = (value[b*SS + idxs[tid]] != 0);
    __syncthreads();
    for (int i = tid; i < 64*64; i += 256) {
        int w = i >> 6, d = i & 63;
        size_t base = ((size_t)(b*SS + idxs[w]))*QKS + h*DD + d;
        qb[w*65 + d] = q[base];
        kb[w*65 + d] = k[base];
        vb[w*65 + d] = v[base];
    }
    __syncthreads();
    int tw = (tid >> 4) * 4;
    int tx = (tid & 15) * 4;
    float a2[4][4];
#pragma unroll
    for (int i = 0; i < 4; i++)
#pragma unroll
        for (int j = 0; j < 4; j++) a2[i][j] = 0.0f;
    for (int kk = 0; kk < 64; kk++) {
        float qv[4], kv[4];
#pragma unroll
        for (int i = 0; i < 4; i++) qv[i] = qb[(tw+i)*65 + kk];
#pragma unroll
        for (int j = 0; j < 4; j++) kv[j] = kb[(tx+j)*65 + kk];
#pragma unroll
        for (int i = 0; i < 4; i++)
#pragma unroll
            for (int j = 0; j < 4; j++) a2[i][j] += qv[i]*kv[j];
    }
#pragma unroll
    for (int i = 0; i < 4; i++)
#pragma unroll
        for (int j = 0; j < 4; j++) {
            bool allowed = (idxs[tw+i] >= idxs[tx+j]) && kms[tx+j];
            sc[(tw+i)*65 + tx+j] = allowed ? a2[i][j]*0.125f : -1e9f;
        }
    __syncthreads();
    {
        int row = tid >> 2;
        int c0 = (tid & 3) * 16;
        float* sr = sc + row*65 + c0;
        float mx = -INFINITY;
#pragma unroll
        for (int j = 0; j < 16; j++) mx = fmaxf(mx, sr[j]);
        mx = fmaxf(mx, __shfl_xor_sync(0xffffffffu, mx, 1));
        mx = fmaxf(mx, __shfl_xor_sync(0xffffffffu, mx, 2));
        float e[16];
        float sum = 0.0f;
#pragma unroll
        for (int j = 0; j < 16; j++) { e[j] = __expf(sr[j] - mx); sum += e[j]; }
        sum += __shfl_xor_sync(0xffffffffu, sum, 1);
        sum += __shfl_xor_sync(0xffffffffu, sum, 2);
        float inv = 1.0f / sum;
#pragma unroll
        for (int j = 0; j < 16; j++) sr[j] = e[j] * inv;
    }
    __syncthreads();
    float o2[4][4];
#pragma unroll
    for (int i = 0; i < 4; i++)
#pragma unroll
        for (int j = 0; j < 4; j++) o2[i][j] = 0.0f;
    for (int xx = 0; xx < 64; xx++) {
        float sv[4], vv[4];
#pragma unroll
        for (int i = 0; i < 4; i++) sv[i] = sc[(tw+i)*65 + xx];
#pragma unroll
        for (int j = 0; j < 4; j++) vv[j] = vb[xx*65 + tx+j];
#pragma unroll
        for (int i = 0; i < 4; i++)
#pragma unroll
            for (int j = 0; j < 4; j++) o2[i][j] += sv[i]*vv[j];
    }
#pragma unroll
    for (int i = 0; i < 4; i++)
#pragma unroll
        for (int j = 0; j < 4; j++)
            atomicAdd(&attout[((size_t)(b*SS + idxs[tw+i]))*EE + h*DD + tx+j], o2[i][j]);
    if (tid < 64) atomicAdd(&cnt[(size_t)(b*SS + idxs[tid])*HH + h], 1.0f);
}

// ---------------- scatter-mean normalization -> split bf16; zeroes attout/cnt in place ----------------
__global__ void norm_attout_kernel(float* __restrict__ attout, float* __restrict__ cnt,
                                   __nv_bfloat16* __restrict__ oh, __nv_bfloat16* __restrict__ ol) {
    int i = blockIdx.x*256 + threadIdx.x;
    int row = i >> 9;
    int h = (i & 511) >> 6;
    float c = cnt[(size_t)row*HH + h];
    float val = attout[i] / fmaxf(c, 1.0f);
    __nv_bfloat16 hh2, ll2;
    split1(val, hh2, ll2);
    oh[i] = hh2; ol[i] = ll2;
    attout[i] = 0.0f;
    __syncthreads();
    if ((i & 63) == 0) cnt[(size_t)row*HH + h] = 0.0f;
}

// ---------------- head: logits = x @ head_w.T  (N=17), warp per row ----------------
__global__ void head_kernel(const float* __restrict__ x, const float* __restrict__ hw,
                            float* __restrict__ out) {
    int gw = (blockIdx.x*256 + threadIdx.x) >> 5;
    int lane = threadIdx.x & 31;
    if (gw >= MM) return;
    const float* xp = x + (size_t)gw*EE;
    float xr[16];
#pragma unroll
    for (int i = 0; i < 16; i++) xr[i] = xp[lane + i*32];
    for (int o = 0; o < NVOC; o++) {
        const float* w = hw + o*EE;
        float s = 0.0f;
#pragma unroll
        for (int i = 0; i < 16; i++) s += xr[i]*w[lane + i*32];
#pragma unroll
        for (int off = 16; off; off >>= 1) s += __shfl_xor_sync(0xffffffffu, s, off);
        if (lane == 0) out[(size_t)gw*NVOC + o] = s;
    }
}

// ---------------- host orchestration ----------------
extern "C" void kernel_launch(void* const* d_in, const int* in_sizes, int n_in,
                              void* d_out, int out_size) {
    const int*   value     = (const int*)d_in[0];
    const int*   depth     = (const int*)d_in[1];
    const int*   pos       = (const int*)d_in[2];
    const float* sos       = (const float*)d_in[3];
    const float* tok_emb   = (const float*)d_in[4];
    const float* depth_emb = (const float*)d_in[5];
    const float* pos_emb   = (const float*)d_in[6];
    const float* ln1_s     = (const float*)d_in[7];
    const float* ln1_b     = (const float*)d_in[8];
    const float* Wq        = (const float*)d_in[9];
    const float* Wk        = (const float*)d_in[10];
    const float* Wv        = (const float*)d_in[11];
    const float* Wo        = (const float*)d_in[12];
    const float* means     = (const float*)d_in[13];
    const float* ln2_s     = (const float*)d_in[14];
    const float* ln2_b     = (const float*)d_in[15];
    const float* W1        = (const float*)d_in[16];
    const float* b1        = (const float*)d_in[17];
    const float* W2        = (const float*)d_in[18];
    const float* b2        = (const float*)d_in[19];
    const float* head_w    = (const float*)d_in[20];
    float* out = (float*)d_out;

    float *x, *qkv, *dists, *attout, *cnt;
    __nv_bfloat16 *hh, *hl, *th, *tl, *aoh, *aol;
    uint32_t *Wqkvh, *Wqkvl, *Woh, *Wol, *W1h, *W1l, *W2h, *W2l;
    cudaGetSymbolAddress((void**)&x, g_x);
    cudaGetSymbolAddress((void**)&qkv, g_qkv);
    cudaGetSymbolAddress((void**)&dists, g_dists);
    cudaGetSymbolAddress((void**)&attout, g_attout);
    cudaGetSymbolAddress((void**)&cnt, g_cnt);
    cudaGetSymbolAddress((void**)&hh, g_hh);   cudaGetSymbolAddress((void**)&hl, g_hl);
    cudaGetSymbolAddress((void**)&th, g_th);   cudaGetSymbolAddress((void**)&tl, g_tl);
    cudaGetSymbolAddress((void**)&aoh, g_aoh); cudaGetSymbolAddress((void**)&aol, g_aol);
    cudaGetSymbolAddress((void**)&Wqkvh, g_Wqkvh); cudaGetSymbolAddress((void**)&Wqkvl, g_Wqkvl);
    cudaGetSymbolAddress((void**)&Woh, g_Woh); cudaGetSymbolAddress((void**)&Wol, g_Wol);
    cudaGetSymbolAddress((void**)&W1h, g_W1h); cudaGetSymbolAddress((void**)&W1l, g_W1l);
    cudaGetSymbolAddress((void**)&W2h, g_W2h); cudaGetSymbolAddress((void**)&W2l, g_W2l);

    const int ATTN_SMEM = 4 * 64 * 65 * (int)sizeof(float);
    cudaFuncSetAttribute(topk_attn_kernel, cudaFuncAttributeMaxDynamicSharedMemorySize, ATTN_SMEM);
    const int DIST_SMEM = (128*65 + 64*64 + 64 + 128) * (int)sizeof(float);
    cudaFuncSetAttribute(dist_kernel, cudaFuncAttributeMaxDynamicSharedMemorySize, DIST_SMEM);
    cudaFuncSetAttribute(bf3_gemm<0,0,false>, cudaFuncAttributeMaxDynamicSharedMemorySize, GEMM_SMEM);
    cudaFuncSetAttribute(bf3_gemm<0,1,false>, cudaFuncAttributeMaxDynamicSharedMemorySize, GEMM_SMEM);
    cudaFuncSetAttribute(bf3_gemm<1,2,true>,  cudaFuncAttributeMaxDynamicSharedMemorySize, GEMM_SMEM);
    cudaFuncSetAttribute(bf3_gemm<0,1,true>,  cudaFuncAttributeMaxDynamicSharedMemorySize, GEMM_SMEM);

    split_all_kernel<<<SPLIT_BLOCKS, 256>>>(Wq, Wk, Wv, Wo, W1, W2,
                                            Wqkvh, Wqkvl, Woh, Wol, W1h, W1l, W2h, W2l);
    embed_kernel<<<MM, 128>>>(value, depth, pos, sos, tok_emb, depth_emb, pos_emb, x);
    cudaMemsetAsync(attout, 0, (size_t)MM*EE*sizeof(float));
    cudaMemsetAsync(cnt, 0, (size_t)MM*HH*sizeof(float));

    dim3 gE(EE/128, MM/128);     // 4 x 128
    dim3 gQ(QKS/128, MM/128);    // 12 x 128
    dim3 gF(FF/128, MM/128);     // 16 x 128
    dim3 gD(SS/128, BB*HH);      // 32 x 32

    for (int l = 0; l < LL; l++) {
        size_t oQ = (size_t)l*(EE/2)*QKS;
        size_t oE = (size_t)l*(EE/2)*EE;
        size_t oF1 = (size_t)l*(EE/2)*FF;
        size_t oF2 = (size_t)l*(FF/2)*EE;
        const float* ml = means + (size_t)l*HH*CC*DD;
        float* q = qkv;
        float* k = qkv + EE;
        float* v = qkv + 2*EE;

        ln_kernel<<<MM/8, 256>>>(x, ln1_s + l*EE, ln1_b + l*EE, hh, hl);
        bf3_gemm<0,0,false><<<gQ, 256, GEMM_SMEM>>>(hh, hl, Wqkvh+oQ, Wqkvl+oQ, nullptr, qkv, nullptr, nullptr, MM, QKS, EE);

        dist_kernel<<<gD, 256, DIST_SMEM>>>(q, ml, dists);
        topk_attn_kernel<<<BB*HH*CC, 256, ATTN_SMEM>>>(dists, q, k, v, value, attout, cnt);
        norm_attout_kernel<<<(MM*EE)/256, 256>>>(attout, cnt, aoh, aol);

        bf3_gemm<0,1,false><<<gE, 256, GEMM_SMEM>>>(aoh, aol, Woh+oE, Wol+oE, nullptr, x, nullptr, nullptr, MM, EE, EE);

        ln_kernel<<<MM/8, 256>>>(x, ln2_s + l*EE, ln2_b + l*EE, hh, hl);
        bf3_gemm<1,2,true><<<gF, 256, GEMM_SMEM>>>(hh, hl, W1h+oF1, W1l+oF1, b1 + l*FF, nullptr, th, tl, MM, FF, EE);
        bf3_gemm<0,1,true><<<gE, 256, GEMM_SMEM>>>(th, tl, W2h+oF2, W2l+oF2, b2 + l*EE, x, nullptr, nullptr, MM, EE, FF);
    }

    head_kernel<<<MM/8, 256>>>(x, head_w, out);
}

// round 15
// speedup vs baseline: 1.0779x; 1.0779x over previous
#include <cuda_runtime.h>
#include <cuda_bf16.h>
#include <math.h>
#include <stdint.h>

// ---------------- problem constants ----------------
#define BB 4
#define SS 4096
#define EE 512
#define HH 8
#define LL 4
#define AA 3
#define WIN 64
#define CC 64           // S / WIN clusters
#define DD 64           // E / H
#define MM (BB*SS)      // 16384 rows
#define FF (4*EE)       // 2048 ffn dim
#define QKS (3*EE)      // fused qkv row stride 1536
#define NVOC 17

// ---------------- scratch (device globals; no allocation allowed) ----------------
__device__ float g_x[MM*EE];
__device__ float g_qkv[MM*QKS];
__device__ float g_dists[BB*HH*CC*SS];
__device__ int   g_idx[BB*HH*CC*WIN];
__device__ float g_attout[MM*EE];
__device__ float g_cnt[MM*HH];
// split activations (A operands)
__device__ __nv_bfloat16 g_hh[MM*EE],  g_hl[MM*EE];
__device__ __nv_bfloat16 g_th[MM*FF],  g_tl[MM*FF];
__device__ __nv_bfloat16 g_aoh[MM*EE], g_aol[MM*EE];
// split weights, pair-interleaved: uint32 [K/2][N] per layer
__device__ uint32_t g_Wqkvh[LL*(EE/2)*QKS], g_Wqkvl[LL*(EE/2)*QKS];
__device__ uint32_t g_Woh[LL*(EE/2)*EE],    g_Wol[LL*(EE/2)*EE];
__device__ uint32_t g_W1h[LL*(EE/2)*FF],    g_W1l[LL*(EE/2)*FF];
__device__ uint32_t g_W2h[LL*(FF/2)*EE],    g_W2l[LL*(FF/2)*EE];

// ---------------- bf16 split helpers ----------------
__device__ __forceinline__ uint32_t packbf(float x, float y) {
    __nv_bfloat162 t = __floats2bfloat162_rn(x, y);
    return *reinterpret_cast<uint32_t*>(&t);
}
__device__ __forceinline__ void split2(float x, float y, uint32_t& hi, uint32_t& lo) {
    float xh = __bfloat162float(__float2bfloat16(x));
    float yh = __bfloat162float(__float2bfloat16(y));
    hi = packbf(x, y);
    lo = packbf(x - xh, y - yh);
}
__device__ __forceinline__ void split1(float x, __nv_bfloat16& h, __nv_bfloat16& l) {
    h = __float2bfloat16(x);
    l = __float2bfloat16(x - __bfloat162float(h));
}

// ---------------- merged weight split prep (single launch) ----------------
__device__ __forceinline__ void split_pi_item(const float* __restrict__ W,
                                              uint32_t* __restrict__ PIh, uint32_t* __restrict__ PIl,
                                              int K, int N, int gid) {
    int i = gid*4;
    int c = i % N;
    int rest = i / N;
    int p = rest % (K/2);
    int l = rest / (K/2);
    const float* w0 = W + ((size_t)l*K + 2*p)*N + c;
    float4 v0 = *(const float4*)w0;
    float4 v1 = *(const float4*)(w0 + N);
    uint32_t h0,l0,h1,l1,h2,l2,h3,l3;
    split2(v0.x, v1.x, h0, l0);
    split2(v0.y, v1.y, h1, l1);
    split2(v0.z, v1.z, h2, l2);
    split2(v0.w, v1.w, h3, l3);
    size_t o = ((size_t)l*(K/2) + p)*N + c;
    *(uint4*)(PIh + o) = make_uint4(h0,h1,h2,h3);
    *(uint4*)(PIl + o) = make_uint4(l0,l1,l2,l3);
}

#define SPLIT_BLOCKS 6144
__global__ void split_all_kernel(const float* __restrict__ Wq, const float* __restrict__ Wk,
                                 const float* __restrict__ Wv, const float* __restrict__ Wo,
                                 const float* __restrict__ W1, const float* __restrict__ W2,
                                 uint32_t* __restrict__ Wqkvh, uint32_t* __restrict__ Wqkvl,
                                 uint32_t* __restrict__ Woh, uint32_t* __restrict__ Wol,
                                 uint32_t* __restrict__ W1h, uint32_t* __restrict__ W1l,
                                 uint32_t* __restrict__ W2h, uint32_t* __restrict__ W2l) {
    int blk = blockIdx.x;
    int tid = threadIdx.x;
    if (blk < 1536) {
        int gid = blk*256 + tid;
        int i = gid*4;
        int c = i % QKS;
        int rest = i / QKS;
        int p = rest % (EE/2);
        int l = rest / (EE/2);
        const float* src; int cc = c;
        if (c < EE) src = Wq;
        else if (c < 2*EE) { src = Wk; cc = c - EE; }
        else { src = Wv; cc = c - 2*EE; }
        const float* w0 = src + ((size_t)l*EE + 2*p)*EE + cc;
        float4 v0 = *(const float4*)w0;
        float4 v1 = *(const float4*)(w0 + EE);
        uint32_t h0,l0,h1,l1,h2,l2,h3,l3;
        split2(v0.x, v1.x, h0, l0);
        split2(v0.y, v1.y, h1, l1);
        split2(v0.z, v1.z, h2, l2);
        split2(v0.w, v1.w, h3, l3);
        size_t o = ((size_t)l*(EE/2) + p)*QKS + c;
        *(uint4*)(Wqkvh + o) = make_uint4(h0,h1,h2,h3);
        *(uint4*)(Wqkvl + o) = make_uint4(l0,l1,l2,l3);
    } else if (blk < 2048) {
        split_pi_item(Wo, Woh, Wol, EE, EE, (blk-1536)*256 + tid);
    } else if (blk < 4096) {
        split_pi_item(W1, W1h, W1l, EE, FF, (blk-2048)*256 + tid);
    } else {
        split_pi_item(W2, W2h, W2l, FF, EE, (blk-4096)*256 + tid);
    }
}

// ---------------- embedding + shift-right ----------------
__global__ void embed_kernel(const int* __restrict__ value, const int* __restrict__ depth,
                             const int* __restrict__ pos, const float* __restrict__ sos,
                             const float* __restrict__ tok, const float* __restrict__ dep,
                             const float* __restrict__ pemb, float* __restrict__ x) {
    int row = blockIdx.x;
    int t = row & (SS - 1);
    if (t == 0) {
        for (int e = threadIdx.x; e < EE; e += blockDim.x) x[(size_t)row*EE + e] = sos[e];
        return;
    }
    int pr = row - 1;
    int v  = value[pr], dp = depth[pr];
    int p0 = pos[pr*AA+0], p1 = pos[pr*AA+1], p2 = pos[pr*AA+2];
    for (int e = threadIdx.x; e < EE; e += blockDim.x) {
        float s = tok[v*EE+e] + dep[dp*EE+e]
                + pemb[(0*65 + p0)*EE + e]
                + pemb[(1*65 + p1)*EE + e]
                + pemb[(2*65 + p2)*EE + e];
        x[(size_t)row*EE + e] = s;
    }
}

// ---------------- layernorm: warp per row, no smem ----------------
__global__ void ln_kernel(const float* __restrict__ x, const float* __restrict__ sc,
                          const float* __restrict__ bi,
                          __nv_bfloat16* __restrict__ oh, __nv_bfloat16* __restrict__ ol) {
    int warp = threadIdx.x >> 5, lane = threadIdx.x & 31;
    int row = blockIdx.x*8 + warp;
    const float4* xr = (const float4*)(x + (size_t)row*EE);
    float4 v[4];
    float s = 0.0f, q2 = 0.0f;
#pragma unroll
    for (int i = 0; i < 4; i++) {
        v[i] = xr[lane + 32*i];
        s  += v[i].x + v[i].y + v[i].z + v[i].w;
        q2 += v[i].x*v[i].x + v[i].y*v[i].y + v[i].z*v[i].z + v[i].w*v[i].w;
    }
#pragma unroll
    for (int o = 16; o; o >>= 1) {
        s  += __shfl_xor_sync(0xffffffffu, s, o);
        q2 += __shfl_xor_sync(0xffffffffu, q2, o);
    }
    float m = s * (1.0f/EE);
    float r = rsqrtf(q2 * (1.0f/EE) - m*m + 1e-5f);
#pragma unroll
    for (int i = 0; i < 4; i++) {
        int c4 = (lane + 32*i) * 4;
        float y0 = (v[i].x - m)*r*sc[c4+0] + bi[c4+0];
        float y1 = (v[i].y - m)*r*sc[c4+1] + bi[c4+1];
        float y2 = (v[i].z - m)*r*sc[c4+2] + bi[c4+2];
        float y3 = (v[i].w - m)*r*sc[c4+3] + bi[c4+3];
        uint32_t hA, lA, hB, lB;
        split2(y0, y1, hA, lA);
        split2(y2, y3, hB, lB);
        *(uint2*)(oh + (size_t)row*EE + c4) = make_uint2(hA, hB);
        *(uint2*)(ol + (size_t)row*EE + c4) = make_uint2(lA, lB);
    }
}

// ---------------- gelu ----------------
__device__ __forceinline__ float gelu_f(float x) {
    float x3 = x*x*x;
    return 0.5f*x*(1.0f + tanhf(0.7978845608028654f*(x + 0.044715f*x3)));
}

__device__ __forceinline__ void mma_bf16(float d[4], const uint32_t a[4], const uint32_t b[2]) {
    asm volatile(
        "mma.sync.aligned.m16n8k16.row.col.f32.bf16.bf16.f32 "
        "{%0,%1,%2,%3}, {%4,%5,%6,%7}, {%8,%9}, {%0,%1,%2,%3};\n"
        : "+f"(d[0]), "+f"(d[1]), "+f"(d[2]), "+f"(d[3])
        : "r"(a[0]), "r"(a[1]), "r"(a[2]), "r"(a[3]), "r"(b[0]), "r"(b[1]));
}

__device__ __forceinline__ void ldsm4(uint32_t f[4], uint32_t smaddr) {
    asm volatile("ldmatrix.sync.aligned.m8n8.x4.shared.b16 {%0,%1,%2,%3}, [%4];"
                 : "=r"(f[0]), "=r"(f[1]), "=r"(f[2]), "=r"(f[3]) : "r"(smaddr));
}

__device__ __forceinline__ void cpa16(uint32_t dst, const void* src) {
    asm volatile("cp.async.cg.shared.global [%0], [%1], 16;" :: "r"(dst), "l"(src));
}
#define CP_COMMIT() asm volatile("cp.async.commit_group;")
#define CP_WAIT2()  asm volatile("cp.async.wait_group 2;")

// ---------------- split-bf16 tensor GEMM: 4-stage cp.async, per-ni B frags ----------------
#define AST 12
#define BST 136
#define STA (128*AST)
#define STB (8*BST)
#define NSTG 4
#define GEMM_SMEM ((NSTG*(STA*2 + STB*2))*4)

template<int ACT, int OUTMODE, bool HASB>
__global__ void __launch_bounds__(256,2) bf3_gemm(
    const __nv_bfloat16* __restrict__ Ah, const __nv_bfloat16* __restrict__ Al,
    const uint32_t* __restrict__ Bh, const uint32_t* __restrict__ Bl,
    const float* __restrict__ bias,
    float* __restrict__ C,
    __nv_bfloat16* __restrict__ Ch, __nv_bfloat16* __restrict__ Cl,
    int M, int N, int K)
{
    extern __shared__ uint32_t gsm[];
    uint32_t* AsH = gsm;
    uint32_t* AsL = AsH + NSTG*STA;
    uint32_t* BsH = AsL + NSTG*STA;
    uint32_t* BsL = BsH + NSTG*STB;

    int tid = threadIdx.x;
    int lane = tid & 31;
    int warp = tid >> 5;
    int wm = (warp >> 2) * 64;
    int wn = (warp & 3) * 32;
    int bm = blockIdx.y * 128, bn = blockIdx.x * 128;

    float acc[4][4][4];
#pragma unroll
    for (int mi = 0; mi < 4; mi++)
#pragma unroll
        for (int ni = 0; ni < 4; ni++)
#pragma unroll
            for (int r = 0; r < 4; r++) acc[mi][ni][r] = 0.0f;

    int a_r = tid >> 1, a_h = (tid & 1) * 8;
    int b_p = tid >> 5, b_cg = (tid & 31) * 4;
    const __nv_bfloat16* Abh = Ah + (size_t)bm*K + (size_t)a_r*K + a_h;
    const __nv_bfloat16* Abl = Al + (size_t)bm*K + (size_t)a_r*K + a_h;
    const uint32_t* Bbh = Bh + (size_t)b_p*N + bn + b_cg;
    const uint32_t* Bbl = Bl + (size_t)b_p*N + bn + b_cg;

    uint32_t awH = (uint32_t)__cvta_generic_to_shared(AsH) + (a_r*AST + (a_h>>1))*4;
    uint32_t awL = (uint32_t)__cvta_generic_to_shared(AsL) + (a_r*AST + (a_h>>1))*4;
    uint32_t bwH = (uint32_t)__cvta_generic_to_shared(BsH) + (b_p*BST + b_cg)*4;
    uint32_t bwL = (uint32_t)__cvta_generic_to_shared(BsL) + (b_p*BST + b_cg)*4;

    int nk = K / 16;

#define ISSUE(S, K0)                                              \
    {                                                             \
        cpa16(awH + (S)*STA*4, Abh + (K0));                       \
        cpa16(awL + (S)*STA*4, Abl + (K0));                       \
        cpa16(bwH + (S)*STB*4, Bbh + (size_t)((K0)>>1)*N);        \
        cpa16(bwL + (S)*STB*4, Bbl + (size_t)((K0)>>1)*N);        \
    }

    ISSUE(0, 0)  CP_COMMIT();
    ISSUE(1, 16) CP_COMMIT();
    ISSUE(2, 32) CP_COMMIT();

    int l_row = wm + (lane & 7) + ((lane >> 3) & 1) * 8;
    int l_kp  = ((lane >> 4) & 1) * 4;
    uint32_t aoffH = (uint32_t)__cvta_generic_to_shared(AsH) + (l_row*AST + l_kp)*4;
    uint32_t aoffL = (uint32_t)__cvta_generic_to_shared(AsL) + (l_row*AST + l_kp)*4;

    int bc0 = wn + (lane >> 2);
    int bp0 = lane & 3;

    for (int it = 0; it < nk; it++) {
        int buf = it & (NSTG-1);
        CP_WAIT2();
        __syncthreads();
        uint32_t afh[4][4], afl[4][4];
        uint32_t aH = aoffH + (uint32_t)buf*STA*4;
        uint32_t aL = aoffL + (uint32_t)buf*STA*4;
#pragma unroll
        for (int mi = 0; mi < 4; mi++) {
            ldsm4(afh[mi], aH + (uint32_t)(mi*16*AST*4));
            ldsm4(afl[mi], aL + (uint32_t)(mi*16*AST*4));
        }
        if (it + 3 < nk) ISSUE((it+3) & (NSTG-1), (it+3)*16)
        CP_COMMIT();
        const uint32_t* bsH = BsH + buf*STB;
        const uint32_t* bsL = BsL + buf*STB;
        // per-ni B fragments: only 4 B regs live at a time
#pragma unroll
        for (int ni = 0; ni < 4; ni++) {
            int base = bp0*BST + bc0 + ni*8;
            uint32_t bfh[2], bfl[2];
            bfh[0] = bsH[base];
            bfh[1] = bsH[base + 4*BST];
            bfl[0] = bsL[base];
            bfl[1] = bsL[base + 4*BST];
#pragma unroll
            for (int mi = 0; mi < 4; mi++) {
                mma_bf16(acc[mi][ni], afl[mi], bfh);
                mma_bf16(acc[mi][ni], afh[mi], bfl);
                mma_bf16(acc[mi][ni], afh[mi], bfh);
            }
        }
    }

#pragma unroll
    for (int mi = 0; mi < 4; mi++) {
        int r0 = bm + wm + mi*16 + (lane >> 2);
#pragma unroll
        for (int ni = 0; ni < 4; ni++) {
            int c0 = bn + wn + ni*8 + (lane & 3)*2;
            float* a = acc[mi][ni];
#pragma unroll
            for (int hr = 0; hr < 2; hr++) {
                int r = r0 + hr*8;
                float v0 = a[hr*2 + 0], v1 = a[hr*2 + 1];
                if (HASB) { v0 += bias[c0]; v1 += bias[c0+1]; }
                if (ACT == 1) { v0 = gelu_f(v0); v1 = gelu_f(v1); }
                size_t o = (size_t)r*N + c0;
                if (OUTMODE == 0) {
                    float2 t2; t2.x = v0; t2.y = v1;
                    *(float2*)&C[o] = t2;
                } else if (OUTMODE == 1) {
                    float2 old = *(float2*)&C[o];
                    old.x += v0; old.y += v1;
                    *(float2*)&C[o] = old;
                } else {
                    uint32_t hh2, ll2;
                    split2(v0, v1, hh2, ll2);
                    *(uint32_t*)&Ch[o] = hh2;
                    *(uint32_t*)&Cl[o] = ll2;
                }
            }
        }
    }
}

// ---------------- fused qnorm + cluster distances (tiled; q has QKS stride) ----------------
__global__ void dist_kernel(const float* __restrict__ q, const float* __restrict__ means_l,
                            float* __restrict__ dists) {
    extern __shared__ float dsm[];
    float* qs = dsm;
    float* ms = qs + 128*65;
    float* mn = ms + 64*64;
    float* qn = mn + 64;
    int tile = blockIdx.x;
    int bh = blockIdx.y;
    int h = bh & 7, b = bh >> 3;
    int n0 = tile * 128;
    int tid = threadIdx.x;
    for (int i = tid; i < 64*64; i += 256) ms[i] = means_l[h*64*64 + i];
    for (int i = tid; i < 128*16; i += 256) {
        int r = i >> 4, c4 = (i & 15) * 4;
        float4 v = *(const float4*)(q + ((size_t)(b*SS + n0 + r))*QKS + h*DD + c4);
        float* dst = qs + r*65 + c4;
        dst[0]=v.x; dst[1]=v.y; dst[2]=v.z; dst[3]=v.w;
    }
    __syncthreads();
    if (tid < 64) {
        float s = 0; const float* mr = ms + tid*64;
#pragma unroll 16
        for (int d = 0; d < 64; d++) s += mr[d]*mr[d];
        mn[tid] = 1.0f/(sqrtf(s) + 1e-8f);
    } else if (tid >= 128) {
        int r = tid - 128;
        float s = 0; const float* qr = qs + r*65;
#pragma unroll 16
        for (int d = 0; d < 64; d++) s += qr[d]*qr[d];
        qn[r] = 1.0f/(sqrtf(s) + 1e-8f);
    }
    __syncthreads();
    int nl = tid & 127;
    int c0 = (tid >> 7) * 32;
    float acc[32];
#pragma unroll
    for (int c = 0; c < 32; c++) acc[c] = 0.0f;
    for (int dc = 0; dc < 64; dc += 16) {
        float qreg[16];
#pragma unroll
        for (int d = 0; d < 16; d++) qreg[d] = qs[nl*65 + dc + d];
#pragma unroll
        for (int c = 0; c < 32; c++) {
            const float* mr = ms + (c0 + c)*64 + dc;
            float s = acc[c];
#pragma unroll
            for (int d = 0; d < 16; d++) s += qreg[d]*mr[d];
            acc[c] = s;
        }
    }
    float qi = qn[nl];
#pragma unroll
    for (int c = 0; c < 32; c++) {
        int cc = c0 + c;
        dists[((size_t)bh*CC + cc)*SS + n0 + nl] = acc[c]*mn[cc]*qi;
    }
}

// ---------------- radix-select top-64 (exact, ties -> smallest index) ----------------
__global__ void topk_kernel(const float* __restrict__ dists, int* __restrict__ idxout) {
    __shared__ uint32_t keys[SS];
    __shared__ int hist[256];
    __shared__ int ties[SS];
    __shared__ int rmin[256];
    __shared__ int s_chosen, s_rem, s_cntgt, s_ntie, s_pick;
    int blk = blockIdx.x, tid = threadIdx.x;
    const float* drow = dists + (size_t)blk*SS;
    for (int n = tid; n < SS; n += 256) {
        uint32_t u = __float_as_uint(drow[n]);
        keys[n] = (u & 0x80000000u) ? ~u : (u | 0x80000000u);
    }
    uint32_t prefix = 0, maskhi = 0;
    int rem = WIN;
    for (int p = 0; p < 4; p++) {
        int shift = 24 - 8*p;
        hist[tid] = 0;
        __syncthreads();
        for (int n = tid; n < SS; n += 256) {
            uint32_t kk = keys[n];
            if ((kk & maskhi) == prefix) atomicAdd(&hist[(kk >> shift) & 255], 1);
        }
        __syncthreads();
        if (tid == 0) {
            int cum = 0, bsel = 255;
            for (; bsel >= 0; bsel--) { cum += hist[bsel]; if (cum >= rem) break; }
            s_chosen = bsel; s_rem = rem - (cum - hist[bsel]);
        }
        __syncthreads();
        prefix |= ((uint32_t)s_chosen) << shift;
        maskhi |= 0xFFu << shift;
        rem = s_rem;
        __syncthreads();
    }
    uint32_t T = prefix;
    if (tid == 0) { s_cntgt = 0; s_ntie = 0; }
    __syncthreads();
    int* orow = idxout + blk*WIN;
    for (int n = tid; n < SS; n += 256) {
        uint32_t kk = keys[n];
        if (kk > T) { int pp = atomicAdd(&s_cntgt, 1); orow[pp] = n; }
        else if (kk == T) { int pp = atomicAdd(&s_ntie, 1); ties[pp] = n; }
    }
    __syncthreads();
    int cntgt = s_cntgt;
    int need = WIN - cntgt;
    int ntie = s_ntie;
    if (need > 0) {
        if (need == ntie) {
            for (int j = tid; j < need; j += 256) orow[cntgt + j] = ties[j];
        } else {
            int last = -1;
            for (int j = 0; j < need; j++) {
                int mymin = 0x7FFFFFFF;
                for (int t2 = tid; t2 < ntie; t2 += 256) {
                    int vv = ties[t2];
                    if (vv > last && vv < mymin) mymin = vv;
                }
                rmin[tid] = mymin;
                __syncthreads();
                for (int off = 128; off; off >>= 1) {
                    if (tid < off) rmin[tid] = min(rmin[tid], rmin[tid+off]);
                    __syncthreads();
                }
                if (tid == 0) { orow[cntgt + j] = rmin[0]; s_pick = rmin[0]; }
                __syncthreads();
                last = s_pick;
            }
        }
    }
}

// ---------------- bucket attention (register-tiled 4x4; parallel softmax) ----------------
__global__ void bucket_attn_kernel(const float* __restrict__ q, const float* __restrict__ k,
                                   const float* __restrict__ v, const int* __restrict__ value,
                                   const int* __restrict__ idxin, float* __restrict__ attout,
                                   float* __restrict__ cnt) {
    extern __shared__ float sm[];
    float* qb = sm;
    float* kb = qb + 64*65;
    float* vb = kb + 64*65;
    float* sc = vb + 64*65;
    __shared__ int idxs[64];
    __shared__ int kms[64];
    int blk = blockIdx.x;
    int bh = blk / CC; int h = bh % HH; int b = bh / HH;
    int tid = threadIdx.x;
    if (tid < 64) {
        int t = idxin[blk*WIN + tid];
        idxs[tid] = t;
        kms[tid] = (value[b*SS + t] != 0);
    }
    __syncthreads();
    for (int i = tid; i < 64*64; i += 256) {
        int w = i >> 6, d = i & 63;
        size_t base = ((size_t)(b*SS + idxs[w]))*QKS + h*DD + d;
        qb[w*65 + d] = q[base];
        kb[w*65 + d] = k[base];
        vb[w*65 + d] = v[base];
    }
    __syncthreads();
    int tw = (tid >> 4) * 4;
    int tx = (tid & 15) * 4;
    float a2[4][4];
#pragma unroll
    for (int i = 0; i < 4; i++)
#pragma unroll
        for (int j = 0; j < 4; j++) a2[i][j] = 0.0f;
    for (int kk = 0; kk < 64; kk++) {
        float qv[4], kv[4];
#pragma unroll
        for (int i = 0; i < 4; i++) qv[i] = qb[(tw+i)*65 + kk];
#pragma unroll
        for (int j = 0; j < 4; j++) kv[j] = kb[(tx+j)*65 + kk];
#pragma unroll
        for (int i = 0; i < 4; i++)
#pragma unroll
            for (int j = 0; j < 4; j++) a2[i][j] += qv[i]*kv[j];
    }
#pragma unroll
    for (int i = 0; i < 4; i++)
#pragma unroll
        for (int j = 0; j < 4; j++) {
            bool allowed = (idxs[tw+i] >= idxs[tx+j]) && kms[tx+j];
            sc[(tw+i)*65 + tx+j] = allowed ? a2[i][j]*0.125f : -1e9f;
        }
    __syncthreads();
    {
        int row = tid >> 2;
        int c0 = (tid & 3) * 16;
        float* sr = sc + row*65 + c0;
        float mx = -INFINITY;
#pragma unroll
        for (int j = 0; j < 16; j++) mx = fmaxf(mx, sr[j]);
        mx = fmaxf(mx, __shfl_xor_sync(0xffffffffu, mx, 1));
        mx = fmaxf(mx, __shfl_xor_sync(0xffffffffu, mx, 2));
        float e[16];
        float sum = 0.0f;
#pragma unroll
        for (int j = 0; j < 16; j++) { e[j] = __expf(sr[j] - mx); sum += e[j]; }
        sum += __shfl_xor_sync(0xffffffffu, sum, 1);
        sum += __shfl_xor_sync(0xffffffffu, sum, 2);
        float inv = 1.0f / sum;
#pragma unroll
        for (int j = 0; j < 16; j++) sr[j] = e[j] * inv;
    }
    __syncthreads();
    float o2[4][4];
#pragma unroll
    for (int i = 0; i < 4; i++)
#pragma unroll
        for (int j = 0; j < 4; j++) o2[i][j] = 0.0f;
    for (int xx = 0; xx < 64; xx++) {
        float sv[4], vv[4];
#pragma unroll
        for (int i = 0; i < 4; i++) sv[i] = sc[(tw+i)*65 + xx];
#pragma unroll
        for (int j = 0; j < 4; j++) vv[j] = vb[xx*65 + tx+j];
#pragma unroll
        for (int i = 0; i < 4; i++)
#pragma unroll
            for (int j = 0; j < 4; j++) o2[i][j] += sv[i]*vv[j];
    }
#pragma unroll
    for (int i = 0; i < 4; i++)
#pragma unroll
        for (int j = 0; j < 4; j++)
            atomicAdd(&attout[((size_t)(b*SS + idxs[tw+i]))*EE + h*DD + tx+j], o2[i][j]);
    if (tid < 64) atomicAdd(&cnt[(size_t)(b*SS + idxs[tid])*HH + h], 1.0f);
}

// ---------------- scatter-mean normalization -> split bf16; zeroes attout/cnt in place ----------------
__global__ void norm_attout_kernel(float* __restrict__ attout, float* __restrict__ cnt,
                                   __nv_bfloat16* __restrict__ oh, __nv_bfloat16* __restrict__ ol) {
    int i = blockIdx.x*256 + threadIdx.x;
    int row = i >> 9;
    int h = (i & 511) >> 6;
    float c = cnt[(size_t)row*HH + h];
    float val = attout[i] / fmaxf(c, 1.0f);
    __nv_bfloat16 hh2, ll2;
    split1(val, hh2, ll2);
    oh[i] = hh2; ol[i] = ll2;
    attout[i] = 0.0f;
    __syncthreads();
    if ((i & 63) == 0) cnt[(size_t)row*HH + h] = 0.0f;
}

// ---------------- head: logits = x @ head_w.T  (N=17), warp per row ----------------
__global__ void head_kernel(const float* __restrict__ x, const float* __restrict__ hw,
                            float* __restrict__ out) {
    int gw = (blockIdx.x*256 + threadIdx.x) >> 5;
    int lane = threadIdx.x & 31;
    if (gw >= MM) return;
    const float* xp = x + (size_t)gw*EE;
    float xr[16];
#pragma unroll
    for (int i = 0; i < 16; i++) xr[i] = xp[lane + i*32];
    for (int o = 0; o < NVOC; o++) {
        const float* w = hw + o*EE;
        float s = 0.0f;
#pragma unroll
        for (int i = 0; i < 16; i++) s += xr[i]*w[lane + i*32];
#pragma unroll
        for (int off = 16; off; off >>= 1) s += __shfl_xor_sync(0xffffffffu, s, off);
        if (lane == 0) out[(size_t)gw*NVOC + o] = s;
    }
}

// ---------------- host orchestration ----------------
extern "C" void kernel_launch(void* const* d_in, const int* in_sizes, int n_in,
                              void* d_out, int out_size) {
    const int*   value     = (const int*)d_in[0];
    const int*   depth     = (const int*)d_in[1];
    const int*   pos       = (const int*)d_in[2];
    const float* sos       = (const float*)d_in[3];
    const float* tok_emb   = (const float*)d_in[4];
    const float* depth_emb = (const float*)d_in[5];
    const float* pos_emb   = (const float*)d_in[6];
    const float* ln1_s     = (const float*)d_in[7];
    const float* ln1_b     = (const float*)d_in[8];
    const float* Wq        = (const float*)d_in[9];
    const float* Wk        = (const float*)d_in[10];
    const float* Wv        = (const float*)d_in[11];
    const float* Wo        = (const float*)d_in[12];
    const float* means     = (const float*)d_in[13];
    const float* ln2_s     = (const float*)d_in[14];
    const float* ln2_b     = (const float*)d_in[15];
    const float* W1        = (const float*)d_in[16];
    const float* b1        = (const float*)d_in[17];
    const float* W2        = (const float*)d_in[18];
    const float* b2        = (const float*)d_in[19];
    const float* head_w    = (const float*)d_in[20];
    float* out = (float*)d_out;

    float *x, *qkv, *dists, *attout, *cnt;
    int* idxb;
    __nv_bfloat16 *hh, *hl, *th, *tl, *aoh, *aol;
    uint32_t *Wqkvh, *Wqkvl, *Woh, *Wol, *W1h, *W1l, *W2h, *W2l;
    cudaGetSymbolAddress((void**)&x, g_x);
    cudaGetSymbolAddress((void**)&qkv, g_qkv);
    cudaGetSymbolAddress((void**)&dists, g_dists);
    cudaGetSymbolAddress((void**)&idxb, g_idx);
    cudaGetSymbolAddress((void**)&attout, g_attout);
    cudaGetSymbolAddress((void**)&cnt, g_cnt);
    cudaGetSymbolAddress((void**)&hh, g_hh);   cudaGetSymbolAddress((void**)&hl, g_hl);
    cudaGetSymbolAddress((void**)&th, g_th);   cudaGetSymbolAddress((void**)&tl, g_tl);
    cudaGetSymbolAddress((void**)&aoh, g_aoh); cudaGetSymbolAddress((void**)&aol, g_aol);
    cudaGetSymbolAddress((void**)&Wqkvh, g_Wqkvh); cudaGetSymbolAddress((void**)&Wqkvl, g_Wqkvl);
    cudaGetSymbolAddress((void**)&Woh, g_Woh); cudaGetSymbolAddress((void**)&Wol, g_Wol);
    cudaGetSymbolAddress((void**)&W1h, g_W1h); cudaGetSymbolAddress((void**)&W1l, g_W1l);
    cudaGetSymbolAddress((void**)&W2h, g_W2h); cudaGetSymbolAddress((void**)&W2l, g_W2l);

    const int ATTN_SMEM = 4 * 64 * 65 * (int)sizeof(float);
    cudaFuncSetAttribute(bucket_attn_kernel, cudaFuncAttributeMaxDynamicSharedMemorySize, ATTN_SMEM);
    const int DIST_SMEM = (128*65 + 64*64 + 64 + 128) * (int)sizeof(float);
    cudaFuncSetAttribute(dist_kernel, cudaFuncAttributeMaxDynamicSharedMemorySize, DIST_SMEM);
    cudaFuncSetAttribute(bf3_gemm<0,0,false>, cudaFuncAttributeMaxDynamicSharedMemorySize, GEMM_SMEM);
    cudaFuncSetAttribute(bf3_gemm<0,1,false>, cudaFuncAttributeMaxDynamicSharedMemorySize, GEMM_SMEM);
    cudaFuncSetAttribute(bf3_gemm<1,2,true>,  cudaFuncAttributeMaxDynamicSharedMemorySize, GEMM_SMEM);
    cudaFuncSetAttribute(bf3_gemm<0,1,true>,  cudaFuncAttributeMaxDynamicSharedMemorySize, GEMM_SMEM);

    split_all_kernel<<<SPLIT_BLOCKS, 256>>>(Wq, Wk, Wv, Wo, W1, W2,
                                            Wqkvh, Wqkvl, Woh, Wol, W1h, W1l, W2h, W2l);
    embed_kernel<<<MM, 128>>>(value, depth, pos, sos, tok_emb, depth_emb, pos_emb, x);
    cudaMemsetAsync(attout, 0, (size_t)MM*EE*sizeof(float));
    cudaMemsetAsync(cnt, 0, (size_t)MM*HH*sizeof(float));

    dim3 gE(EE/128, MM/128);     // 4 x 128
    dim3 gQ(QKS/128, MM/128);    // 12 x 128
    dim3 gF(FF/128, MM/128);     // 16 x 128
    dim3 gD(SS/128, BB*HH);      // 32 x 32

    for (int l = 0; l < LL; l++) {
        size_t oQ = (size_t)l*(EE/2)*QKS;
        size_t oE = (size_t)l*(EE/2)*EE;
        size_t oF1 = (size_t)l*(EE/2)*FF;
        size_t oF2 = (size_t)l*(FF/2)*EE;
        const float* ml = means + (size_t)l*HH*CC*DD;
        float* q = qkv;
        float* k = qkv + EE;
        float* v = qkv + 2*EE;

        ln_kernel<<<MM/8, 256>>>(x, ln1_s + l*EE, ln1_b + l*EE, hh, hl);
        bf3_gemm<0,0,false><<<gQ, 256, GEMM_SMEM>>>(hh, hl, Wqkvh+oQ, Wqkvl+oQ, nullptr, qkv, nullptr, nullptr, MM, QKS, EE);

        dist_kernel<<<gD, 256, DIST_SMEM>>>(q, ml, dists);
        topk_kernel<<<BB*HH*CC, 256>>>(dists, idxb);

        bucket_attn_kernel<<<BB*HH*CC, 256, ATTN_SMEM>>>(q, k, v, value, idxb, attout, cnt);
        norm_attout_kernel<<<(MM*EE)/256, 256>>>(attout, cnt, aoh, aol);

        bf3_gemm<0,1,false><<<gE, 256, GEMM_SMEM>>>(aoh, aol, Woh+oE, Wol+oE, nullptr, x, nullptr, nullptr, MM, EE, EE);

        ln_kernel<<<MM/8, 256>>>(x, ln2_s + l*EE, ln2_b + l*EE, hh, hl);
        bf3_gemm<1,2,true><<<gF, 256, GEMM_SMEM>>>(hh, hl, W1h+oF1, W1l+oF1, b1 + l*FF, nullptr, th, tl, MM, FF, EE);
        bf3_gemm<0,1,true><<<gE, 256, GEMM_SMEM>>>(th, tl, W2h+oF2, W2l+oF2, b2 + l*EE, x, nullptr, nullptr, MM, EE, FF);
    }

    head_kernel<<<MM/8, 256>>>(x, head_w, out);
}